// round 7
// baseline (speedup 1.0000x reference)
#include <cuda_runtime.h>
#include <cuda_bf16.h>
#include <cstdint>

#define KCODES 512
#define DDIM 64
#define HW 4096
#define MPTS 262144
#define ZQ_ELEMS 16777216
#define TPB 128
#define NBLK (MPTS / TPB)        // 2048 CTAs, 128 points each

// smem layout (bytes)
#define SM_ESQ 0                             // 512 f32
#define SM_MIN 2048                          // 128 f32
#define SM_A 4096                            // 128 rows * 128B bf16 z tile (swizzled)
#define SM_B (SM_A + 16384)                  // 512 rows * 128B bf16 codebook (swizzled)
#define SM_SCORES (SM_B + 65536)             // 128 rows * 1040B bf16 scores
#define SCORE_STRIDE 1040                    // 260 words; 16B multiple (v4-safe)
#define SM_TOTAL (SM_SCORES + 128 * SCORE_STRIDE)  // 219136 B

#define TAU 4.0e-3f

__device__ double g_loss_sum;
__device__ unsigned g_ctr;
__device__ float g_esq[KCODES];
__device__ __align__(16) __nv_bfloat16 g_embbf[KCODES * DDIM];

// ---- prep: e_sq (exact sequential fp32) + bf16 codebook ----
__global__ void vq_prep(const float* __restrict__ emb) {
    int k = threadIdx.x;                     // 512 threads
    const float* row = emb + k * DDIM;
    float q = 0.f;
    #pragma unroll
    for (int d = 0; d < DDIM; d++) {
        float v = row[d];
        q = __fadd_rn(q, __fmul_rn(v, v));
        g_embbf[k * DDIM + d] = __float2bfloat16(v);
    }
    g_esq[k] = q;
    if (k == 0) { g_loss_sum = 0.0; g_ctr = 0u; }
}

// ---- helpers ----
__device__ __forceinline__ uint32_t smem_u32(const void* p) {
    uint32_t a;
    asm("{ .reg .u64 t; cvta.to.shared.u64 t, %1; cvt.u32.u64 %0, t; }"
        : "=r"(a) : "l"(p));
    return a;
}
// packed bf16x2: lo = a, hi = b
__device__ __forceinline__ uint32_t bf16x2(float a, float b) {
    uint32_t r;
    asm("cvt.rn.bf16x2.f32 %0, %1, %2;" : "=r"(r) : "f"(b), "f"(a));
    return r;
}
__device__ __forceinline__ void ldsm_x4(uint32_t addr, uint32_t& r0, uint32_t& r1,
                                        uint32_t& r2, uint32_t& r3) {
    asm volatile("ldmatrix.sync.aligned.m8n8.x4.shared.b16 {%0,%1,%2,%3}, [%4];"
                 : "=r"(r0), "=r"(r1), "=r"(r2), "=r"(r3) : "r"(addr));
}
__device__ __forceinline__ void mma_bf16(float& d0, float& d1, float& d2, float& d3,
                                         uint32_t a0, uint32_t a1, uint32_t a2, uint32_t a3,
                                         uint32_t b0, uint32_t b1) {
    asm volatile(
        "mma.sync.aligned.m16n8k16.row.col.f32.bf16.bf16.f32 "
        "{%0,%1,%2,%3}, {%4,%5,%6,%7}, {%8,%9}, {%0,%1,%2,%3};"
        : "+f"(d0), "+f"(d1), "+f"(d2), "+f"(d3)
        : "r"(a0), "r"(a1), "r"(a2), "r"(a3), "r"(b0), "r"(b1));
}

__global__ __launch_bounds__(TPB, 1)
void vq_main(const float* __restrict__ z, const float* __restrict__ emb,
             float* __restrict__ out) {
    extern __shared__ char smem[];
    const uint32_t sb = smem_u32(smem);
    const int tid = threadIdx.x;
    const int lane = tid & 31, wid = tid >> 5;
    const int g = lane >> 2, t = lane & 3;
    const int wbase = wid * 32;

    // e_sq -> smem
    float* sm_esq = (float*)(smem + SM_ESQ);
    float* sm_min = (float*)(smem + SM_MIN);
    for (int i = tid; i < KCODES; i += TPB) sm_esq[i] = g_esq[i];

    // Load z (fp32, exact) + z_sq sequential
    const int p  = blockIdx.x * TPB + tid;
    const int n  = p >> 12;
    const int hw = p & (HW - 1);
    const float* zp = z + (size_t)n * (DDIM * HW) + hw;
    float zf[DDIM];
    float S = 0.f;
    #pragma unroll
    for (int d = 0; d < DDIM; d++) {
        float v = zp[d * HW];
        zf[d] = v;
        S = __fadd_rn(S, __fmul_rn(v, v));
    }

    // A tile: row tid, 8 granules of 16B, granule-XOR swizzle
    #pragma unroll
    for (int j = 0; j < 8; j++) {
        uint32_t w0 = bf16x2(zf[8*j+0], zf[8*j+1]);
        uint32_t w1 = bf16x2(zf[8*j+2], zf[8*j+3]);
        uint32_t w2 = bf16x2(zf[8*j+4], zf[8*j+5]);
        uint32_t w3 = bf16x2(zf[8*j+6], zf[8*j+7]);
        uint32_t a = sb + SM_A + (uint32_t)tid * 128 + (uint32_t)((j ^ (tid & 7)) << 4);
        asm volatile("st.shared.v4.b32 [%0], {%1,%2,%3,%4};"
                     :: "r"(a), "r"(w0), "r"(w1), "r"(w2), "r"(w3) : "memory");
    }

    // B tile: 4096 granules, same swizzle
    const uint4* gb = (const uint4*)g_embbf;
    #pragma unroll 4
    for (int it = 0; it < 32; it++) {
        uint32_t i16 = (uint32_t)(it * TPB + tid);
        uint4 v = gb[i16];
        uint32_t row = i16 >> 3, j = i16 & 7;
        uint32_t a = sb + SM_B + row * 128 + (((j ^ (row & 7))) << 4);
        asm volatile("st.shared.v4.b32 [%0], {%1,%2,%3,%4};"
                     :: "r"(a), "r"(v.x), "r"(v.y), "r"(v.z), "r"(v.w) : "memory");
    }
    __syncthreads();

    // A fragments: 2 m-tiles x 4 k-steps, ldmatrix.x4 each
    uint32_t afr[2][4][4];
    {
        const int sub = lane >> 3;
        const int rowo = (lane & 7) + ((sub & 1) << 3);
        #pragma unroll
        for (int m = 0; m < 2; m++) {
            #pragma unroll
            for (int kc = 0; kc < 4; kc++) {
                int row = wbase + 16 * m + rowo;
                int gran = 2 * kc + (sub >> 1);
                uint32_t a = sb + SM_A + (uint32_t)row * 128
                           + (uint32_t)((gran ^ (row & 7)) << 4);
                ldsm_x4(a, afr[m][kc][0], afr[m][kc][1], afr[m][kc][2], afr[m][kc][3]);
            }
        }
    }

    // Pass 1: 64 n-tiles; split-k accumulators for ILP; scores -> bf16 smem; min
    // Score group swizzle: group = (nt - 2g) & 63 makes both store and load
    // phases hit 32 distinct banks (260-word rows: bank = 4*(g+group)+t mod 32).
    const float INF = __int_as_float(0x7f800000);
    float mn0 = INF, mn1 = INF, mn2 = INF, mn3 = INF;
    const int brow = (lane & 7);
    const int bsub = lane >> 3;
    #pragma unroll 1
    for (int nt = 0; nt < 64; nt++) {
        uint32_t b[8];
        #pragma unroll
        for (int kk = 0; kk < 2; kk++) {
            int row = nt * 8 + brow;
            int gran = 4 * kk + bsub;
            uint32_t a = sb + SM_B + (uint32_t)row * 128
                       + (uint32_t)((gran ^ (row & 7)) << 4);
            ldsm_x4(a, b[4*kk], b[4*kk+1], b[4*kk+2], b[4*kk+3]);
        }
        float2 e2 = *(const float2*)(sm_esq + nt * 8 + 2 * t);
        const uint32_t word = (uint32_t)((((nt - 2 * g) & 63) << 2) + t);
        #pragma unroll
        for (int m = 0; m < 2; m++) {
            float dA0 = 0.f, dA1 = 0.f, dA2 = 0.f, dA3 = 0.f;
            float dB0 = 0.f, dB1 = 0.f, dB2 = 0.f, dB3 = 0.f;
            mma_bf16(dA0, dA1, dA2, dA3, afr[m][0][0], afr[m][0][1], afr[m][0][2], afr[m][0][3], b[0], b[1]);
            mma_bf16(dB0, dB1, dB2, dB3, afr[m][1][0], afr[m][1][1], afr[m][1][2], afr[m][1][3], b[2], b[3]);
            mma_bf16(dA0, dA1, dA2, dA3, afr[m][2][0], afr[m][2][1], afr[m][2][2], afr[m][2][3], b[4], b[5]);
            mma_bf16(dB0, dB1, dB2, dB3, afr[m][3][0], afr[m][3][1], afr[m][3][2], afr[m][3][3], b[6], b[7]);
            float s0 = fmaf(-2.f, dA0 + dB0, e2.x);
            float s1 = fmaf(-2.f, dA1 + dB1, e2.y);
            float s2 = fmaf(-2.f, dA2 + dB2, e2.x);
            float s3 = fmaf(-2.f, dA3 + dB3, e2.y);
            if (m == 0) { mn0 = fminf(mn0, fminf(s0, s1)); mn1 = fminf(mn1, fminf(s2, s3)); }
            else        { mn2 = fminf(mn2, fminf(s0, s1)); mn3 = fminf(mn3, fminf(s2, s3)); }
            int row_lo = wbase + 16 * m + g;
            uint32_t alo = sb + SM_SCORES + (uint32_t)row_lo * SCORE_STRIDE + word * 4;
            uint32_t ahi = alo + 8u * SCORE_STRIDE;
            uint32_t plo = bf16x2(s0, s1);
            uint32_t phi = bf16x2(s2, s3);
            asm volatile("st.shared.b32 [%0], %1;" :: "r"(alo), "r"(plo) : "memory");
            asm volatile("st.shared.b32 [%0], %1;" :: "r"(ahi), "r"(phi) : "memory");
        }
    }

    // min reduce across quad lanes (same g)
    #pragma unroll
    for (int off = 1; off <= 2; off <<= 1) {
        mn0 = fminf(mn0, __shfl_xor_sync(0xffffffffu, mn0, off));
        mn1 = fminf(mn1, __shfl_xor_sync(0xffffffffu, mn1, off));
        mn2 = fminf(mn2, __shfl_xor_sync(0xffffffffu, mn2, off));
        mn3 = fminf(mn3, __shfl_xor_sync(0xffffffffu, mn3, off));
    }
    if (t == 0) {
        sm_min[wbase + g]      = mn0;
        sm_min[wbase + g + 8]  = mn1;
        sm_min[wbase + 16 + g] = mn2;
        sm_min[wbase + 24 + g] = mn3;
    }
    __syncthreads();

    // Pass 2: candidates within tau -> exact sequential fp32 rescore
    const float thr = sm_min[tid] + TAU;
    float bestd = 3.0e38f;
    int bestk = 0;
    const uint32_t srow = sb + SM_SCORES + (uint32_t)tid * SCORE_STRIDE;
    const int x7 = tid & 7;
    #pragma unroll 1
    for (int nt = 0; nt < 64; nt++) {
        uint32_t grp = (uint32_t)((nt - 2 * x7) & 63);
        uint32_t q0, q1, q2, q3;
        asm volatile("ld.shared.v4.b32 {%0,%1,%2,%3}, [%4];"
                     : "=r"(q0), "=r"(q1), "=r"(q2), "=r"(q3)
                     : "r"(srow + (grp << 4)));
        uint32_t qs[4] = {q0, q1, q2, q3};
        #pragma unroll
        for (int tt = 0; tt < 4; tt++) {
            __nv_bfloat162 h2 = *(__nv_bfloat162*)&qs[tt];
            float s0 = __bfloat162float(h2.x);
            float s1 = __bfloat162float(h2.y);
            #pragma unroll
            for (int half = 0; half < 2; half++) {
                float s = half ? s1 : s0;
                if (s < thr) {
                    int k = nt * 8 + 2 * tt + half;
                    const float* er = emb + k * DDIM;
                    float dot = 0.f;
                    #pragma unroll
                    for (int d = 0; d < DDIM; d++)
                        dot = __fmaf_rn(zf[d], er[d], dot);
                    float dist = __fsub_rn(__fadd_rn(S, sm_esq[k]), __fmul_rn(2.0f, dot));
                    if (dist < bestd) { bestd = dist; bestk = k; }  // ascending k ties
                }
            }
        }
    }

    // Epilogue: z_q (straight-through), loss, index
    const float* er = emb + bestk * DDIM;
    float* outz = out + (size_t)n * (DDIM * HW) + hw;
    double lsum = 0.0;
    #pragma unroll
    for (int d = 0; d < DDIM; d++) {
        float e = er[d], v = zf[d];
        outz[d * HW] = __fadd_rn(v, __fsub_rn(e, v));  // fl(z + fl(z_q - z))
        float xx = __fsub_rn(v, e);
        lsum += (double)xx * (double)xx;
    }
    out[ZQ_ELEMS + 1 + p] = (float)bestk;

    #pragma unroll
    for (int off = 16; off > 0; off >>= 1)
        lsum += __shfl_down_sync(0xffffffffu, lsum, off);
    if ((tid & 31) == 0) atomicAdd(&g_loss_sum, lsum);

    // last-block loss finalize
    __threadfence();
    __syncthreads();
    if (tid == 0) {
        unsigned tk = atomicAdd(&g_ctr, 1u);
        if (tk == (unsigned)(NBLK - 1)) {
            double s = atomicAdd(&g_loss_sum, 0.0);
            out[ZQ_ELEMS] = (float)(s / (double)ZQ_ELEMS);
        }
    }
}

extern "C" void kernel_launch(void* const* d_in, const int* in_sizes, int n_in,
                              void* d_out, int out_size) {
    const float* z   = (const float*)d_in[0];   // z_e (64,64,64,64) f32
    const float* emb = (const float*)d_in[1];   // emb_weight (512,64) f32
    float* out = (float*)d_out;

    cudaFuncSetAttribute(vq_main, cudaFuncAttributeMaxDynamicSharedMemorySize, SM_TOTAL);
    vq_prep<<<1, KCODES>>>(emb);
    vq_main<<<NBLK, TPB, SM_TOTAL>>>(z, emb, out);
}

// round 8
// speedup vs baseline: 1.0107x; 1.0107x over previous
#include <cuda_runtime.h>
#include <cuda_bf16.h>
#include <cstdint>

#define KCODES 512
#define DDIM 64
#define HW 4096
#define MPTS 262144
#define ZQ_ELEMS 16777216
#define TPB 256
#define NBLK (MPTS / TPB)        // 1024 CTAs, 256 points each

// smem layout (bytes)
#define SM_ESQ 0                 // 512 f32
#define SM_THR 2048              // 256 f32
#define SM_CNT 3072              // 256 u32
#define SM_CAND 4096             // 256 * 8 u32 = 8192
#define SM_A 12288               // 256 rows * 128B bf16 z tile (swizzled)
#define SM_B 45056               // 512 rows * 128B bf16 codebook (swizzled)
#define SM_TOTAL 110592          // 108 KB -> 2 CTAs/SM

#define TAU 4.0e-3f
#define CAND_MAX 8

__device__ double g_loss_sum;
__device__ unsigned g_ctr;
__device__ float g_esq[KCODES];
__device__ __align__(16) __nv_bfloat16 g_embbf[KCODES * DDIM];

// ---- prep: e_sq (exact sequential fp32) + bf16 codebook ----
__global__ void vq_prep(const float* __restrict__ emb) {
    int k = threadIdx.x;                     // 512 threads
    const float* row = emb + k * DDIM;
    float q = 0.f;
    #pragma unroll
    for (int d = 0; d < DDIM; d++) {
        float v = row[d];
        q = __fadd_rn(q, __fmul_rn(v, v));
        g_embbf[k * DDIM + d] = __float2bfloat16(v);
    }
    g_esq[k] = q;
    if (k == 0) { g_loss_sum = 0.0; g_ctr = 0u; }
}

// ---- helpers ----
__device__ __forceinline__ uint32_t smem_u32(const void* p) {
    uint32_t a;
    asm("{ .reg .u64 t; cvta.to.shared.u64 t, %1; cvt.u32.u64 %0, t; }"
        : "=r"(a) : "l"(p));
    return a;
}
// packed bf16x2: lo = a, hi = b
__device__ __forceinline__ uint32_t bf16x2(float a, float b) {
    uint32_t r;
    asm("cvt.rn.bf16x2.f32 %0, %1, %2;" : "=r"(r) : "f"(b), "f"(a));
    return r;
}
__device__ __forceinline__ void ldsm_x4(uint32_t addr, uint32_t& r0, uint32_t& r1,
                                        uint32_t& r2, uint32_t& r3) {
    asm volatile("ldmatrix.sync.aligned.m8n8.x4.shared.b16 {%0,%1,%2,%3}, [%4];"
                 : "=r"(r0), "=r"(r1), "=r"(r2), "=r"(r3) : "r"(addr));
}
__device__ __forceinline__ void mma_bf16(float& d0, float& d1, float& d2, float& d3,
                                         uint32_t a0, uint32_t a1, uint32_t a2, uint32_t a3,
                                         uint32_t b0, uint32_t b1) {
    asm volatile(
        "mma.sync.aligned.m16n8k16.row.col.f32.bf16.bf16.f32 "
        "{%0,%1,%2,%3}, {%4,%5,%6,%7}, {%8,%9}, {%0,%1,%2,%3};"
        : "+f"(d0), "+f"(d1), "+f"(d2), "+f"(d3)
        : "r"(a0), "r"(a1), "r"(a2), "r"(a3), "r"(b0), "r"(b1));
}

__global__ __launch_bounds__(TPB, 2)
void vq_main(const float* __restrict__ z, const float* __restrict__ emb,
             float* __restrict__ out) {
    extern __shared__ char smem[];
    const uint32_t sb = smem_u32(smem);
    const int tid = threadIdx.x;
    const int lane = tid & 31, wid = tid >> 5;
    const int g = lane >> 2, t = lane & 3;
    const int wbase = wid * 32;

    float* sm_esq = (float*)(smem + SM_ESQ);
    float* sm_thr = (float*)(smem + SM_THR);
    unsigned* sm_cnt = (unsigned*)(smem + SM_CNT);
    unsigned* sm_cand = (unsigned*)(smem + SM_CAND);

    for (int i = tid; i < KCODES; i += TPB) sm_esq[i] = g_esq[i];
    sm_cnt[tid] = 0u;

    const int p  = blockIdx.x * TPB + tid;
    const int n  = p >> 12;
    const int hw = p & (HW - 1);
    const float* zp = z + (size_t)n * (DDIM * HW) + hw;

    // Phase A: stream z -> z_sq (sequential fp32) + bf16 A tile (8 floats live)
    float S = 0.f;
    #pragma unroll
    for (int j = 0; j < 8; j++) {
        float v[8];
        #pragma unroll
        for (int e = 0; e < 8; e++) v[e] = zp[(8 * j + e) * HW];
        #pragma unroll
        for (int e = 0; e < 8; e++) S = __fadd_rn(S, __fmul_rn(v[e], v[e]));
        uint32_t w0 = bf16x2(v[0], v[1]);
        uint32_t w1 = bf16x2(v[2], v[3]);
        uint32_t w2 = bf16x2(v[4], v[5]);
        uint32_t w3 = bf16x2(v[6], v[7]);
        uint32_t a = sb + SM_A + (uint32_t)tid * 128 + (uint32_t)((j ^ (tid & 7)) << 4);
        asm volatile("st.shared.v4.b32 [%0], {%1,%2,%3,%4};"
                     :: "r"(a), "r"(w0), "r"(w1), "r"(w2), "r"(w3) : "memory");
    }

    // B tile: 4096 granules / 256 threads = 16 iters
    const uint4* gb = (const uint4*)g_embbf;
    #pragma unroll 4
    for (int it = 0; it < 16; it++) {
        uint32_t i16 = (uint32_t)(it * TPB + tid);
        uint4 v = gb[i16];
        uint32_t row = i16 >> 3, j = i16 & 7;
        uint32_t a = sb + SM_B + row * 128 + ((j ^ (row & 7)) << 4);
        asm volatile("st.shared.v4.b32 [%0], {%1,%2,%3,%4};"
                     :: "r"(a), "r"(v.x), "r"(v.y), "r"(v.z), "r"(v.w) : "memory");
    }
    __syncthreads();

    // A fragments: 2 m-tiles x 4 k-steps
    uint32_t afr[2][4][4];
    {
        const int sub = lane >> 3;
        const int rowo = (lane & 7) + ((sub & 1) << 3);
        #pragma unroll
        for (int m = 0; m < 2; m++) {
            #pragma unroll
            for (int kc = 0; kc < 4; kc++) {
                int row = wbase + 16 * m + rowo;
                int gran = 2 * kc + (sub >> 1);
                uint32_t a = sb + SM_A + (uint32_t)row * 128
                           + (uint32_t)((gran ^ (row & 7)) << 4);
                ldsm_x4(a, afr[m][kc][0], afr[m][kc][1], afr[m][kc][2], afr[m][kc][3]);
            }
        }
    }

    const int brow = lane & 7;
    const int bsub = lane >> 3;
    const float INF = __int_as_float(0x7f800000);

    // Pass 1: MMA sweep, per-fragment-row min only (no score stash)
    float mn0 = INF, mn1 = INF, mn2 = INF, mn3 = INF;
    #pragma unroll 1
    for (int nt = 0; nt < 64; nt++) {
        uint32_t b[8];
        #pragma unroll
        for (int kk = 0; kk < 2; kk++) {
            int row = nt * 8 + brow;
            int gran = 4 * kk + bsub;
            uint32_t a = sb + SM_B + (uint32_t)row * 128
                       + (uint32_t)((gran ^ (row & 7)) << 4);
            ldsm_x4(a, b[4*kk], b[4*kk+1], b[4*kk+2], b[4*kk+3]);
        }
        float2 e2 = *(const float2*)(sm_esq + nt * 8 + 2 * t);
        #pragma unroll
        for (int m = 0; m < 2; m++) {
            float dA0 = 0.f, dA1 = 0.f, dA2 = 0.f, dA3 = 0.f;
            float dB0 = 0.f, dB1 = 0.f, dB2 = 0.f, dB3 = 0.f;
            mma_bf16(dA0, dA1, dA2, dA3, afr[m][0][0], afr[m][0][1], afr[m][0][2], afr[m][0][3], b[0], b[1]);
            mma_bf16(dB0, dB1, dB2, dB3, afr[m][1][0], afr[m][1][1], afr[m][1][2], afr[m][1][3], b[2], b[3]);
            mma_bf16(dA0, dA1, dA2, dA3, afr[m][2][0], afr[m][2][1], afr[m][2][2], afr[m][2][3], b[4], b[5]);
            mma_bf16(dB0, dB1, dB2, dB3, afr[m][3][0], afr[m][3][1], afr[m][3][2], afr[m][3][3], b[6], b[7]);
            float s0 = fmaf(-2.f, dA0 + dB0, e2.x);
            float s1 = fmaf(-2.f, dA1 + dB1, e2.y);
            float s2 = fmaf(-2.f, dA2 + dB2, e2.x);
            float s3 = fmaf(-2.f, dA3 + dB3, e2.y);
            if (m == 0) { mn0 = fminf(mn0, fminf(s0, s1)); mn1 = fminf(mn1, fminf(s2, s3)); }
            else        { mn2 = fminf(mn2, fminf(s0, s1)); mn3 = fminf(mn3, fminf(s2, s3)); }
        }
    }
    #pragma unroll
    for (int off = 1; off <= 2; off <<= 1) {
        mn0 = fminf(mn0, __shfl_xor_sync(0xffffffffu, mn0, off));
        mn1 = fminf(mn1, __shfl_xor_sync(0xffffffffu, mn1, off));
        mn2 = fminf(mn2, __shfl_xor_sync(0xffffffffu, mn2, off));
        mn3 = fminf(mn3, __shfl_xor_sync(0xffffffffu, mn3, off));
    }
    if (t == 0) {
        sm_thr[wbase + g]      = mn0 + TAU;
        sm_thr[wbase + 8 + g]  = mn1 + TAU;
        sm_thr[wbase + 16 + g] = mn2 + TAU;
        sm_thr[wbase + 24 + g] = mn3 + TAU;
    }
    __syncthreads();

    const float tA = sm_thr[wbase + g];
    const float tB = sm_thr[wbase + 8 + g];
    const float tC = sm_thr[wbase + 16 + g];
    const float tD = sm_thr[wbase + 24 + g];

    // Pass 2: identical MMA sweep (bitwise same scores); push candidates
    #pragma unroll 1
    for (int nt = 0; nt < 64; nt++) {
        uint32_t b[8];
        #pragma unroll
        for (int kk = 0; kk < 2; kk++) {
            int row = nt * 8 + brow;
            int gran = 4 * kk + bsub;
            uint32_t a = sb + SM_B + (uint32_t)row * 128
                       + (uint32_t)((gran ^ (row & 7)) << 4);
            ldsm_x4(a, b[4*kk], b[4*kk+1], b[4*kk+2], b[4*kk+3]);
        }
        float2 e2 = *(const float2*)(sm_esq + nt * 8 + 2 * t);
        #pragma unroll
        for (int m = 0; m < 2; m++) {
            float dA0 = 0.f, dA1 = 0.f, dA2 = 0.f, dA3 = 0.f;
            float dB0 = 0.f, dB1 = 0.f, dB2 = 0.f, dB3 = 0.f;
            mma_bf16(dA0, dA1, dA2, dA3, afr[m][0][0], afr[m][0][1], afr[m][0][2], afr[m][0][3], b[0], b[1]);
            mma_bf16(dB0, dB1, dB2, dB3, afr[m][1][0], afr[m][1][1], afr[m][1][2], afr[m][1][3], b[2], b[3]);
            mma_bf16(dA0, dA1, dA2, dA3, afr[m][2][0], afr[m][2][1], afr[m][2][2], afr[m][2][3], b[4], b[5]);
            mma_bf16(dB0, dB1, dB2, dB3, afr[m][3][0], afr[m][3][1], afr[m][3][2], afr[m][3][3], b[6], b[7]);
            float s0 = fmaf(-2.f, dA0 + dB0, e2.x);
            float s1 = fmaf(-2.f, dA1 + dB1, e2.y);
            float s2 = fmaf(-2.f, dA2 + dB2, e2.x);
            float s3 = fmaf(-2.f, dA3 + dB3, e2.y);
            const float thrLo = m ? tC : tA;
            const float thrHi = m ? tD : tB;
            const int rowLo = wbase + 16 * m + g;
            const int rowHi = rowLo + 8;
            const int kbase = nt * 8 + 2 * t;
            if (s0 < thrLo) { unsigned ix = atomicAdd(&sm_cnt[rowLo], 1u);
                              if (ix < CAND_MAX) sm_cand[rowLo * CAND_MAX + ix] = kbase; }
            if (s1 < thrLo) { unsigned ix = atomicAdd(&sm_cnt[rowLo], 1u);
                              if (ix < CAND_MAX) sm_cand[rowLo * CAND_MAX + ix] = kbase + 1; }
            if (s2 < thrHi) { unsigned ix = atomicAdd(&sm_cnt[rowHi], 1u);
                              if (ix < CAND_MAX) sm_cand[rowHi * CAND_MAX + ix] = kbase; }
            if (s3 < thrHi) { unsigned ix = atomicAdd(&sm_cnt[rowHi], 1u);
                              if (ix < CAND_MAX) sm_cand[rowHi * CAND_MAX + ix] = kbase + 1; }
        }
    }
    __syncthreads();

    // Epilogue: reload exact z (L1-warm), rescore candidates, z_q, loss, index
    float zf[DDIM];
    #pragma unroll
    for (int d = 0; d < DDIM; d++) zf[d] = zp[d * HW];

    float bestd = 3.0e38f;
    int bestk = 0;
    const unsigned cnt = sm_cnt[tid];
    if (cnt <= CAND_MAX) {
        for (unsigned c = 0; c < cnt; c++) {
            int k = (int)sm_cand[tid * CAND_MAX + c];
            const float* er = emb + k * DDIM;
            float dot = 0.f;
            #pragma unroll
            for (int d = 0; d < DDIM; d++)
                dot = __fmaf_rn(zf[d], er[d], dot);
            float dist = __fsub_rn(__fadd_rn(S, sm_esq[k]), __fmul_rn(2.0f, dot));
            if (dist < bestd || (dist == bestd && k < bestk)) { bestd = dist; bestk = k; }
        }
    } else {
        // overflow fallback (statistically never): exact full scan, ascending k
        for (int k = 0; k < KCODES; k++) {
            const float* er = emb + k * DDIM;
            float dot = 0.f;
            #pragma unroll
            for (int d = 0; d < DDIM; d++)
                dot = __fmaf_rn(zf[d], er[d], dot);
            float dist = __fsub_rn(__fadd_rn(S, sm_esq[k]), __fmul_rn(2.0f, dot));
            if (dist < bestd) { bestd = dist; bestk = k; }
        }
    }

    const float* er = emb + bestk * DDIM;
    float* outz = out + (size_t)n * (DDIM * HW) + hw;
    double lsum = 0.0;
    #pragma unroll
    for (int d = 0; d < DDIM; d++) {
        float e = er[d], v = zf[d];
        outz[d * HW] = __fadd_rn(v, __fsub_rn(e, v));  // fl(z + fl(z_q - z))
        float xx = __fsub_rn(v, e);
        lsum += (double)xx * (double)xx;
    }
    out[ZQ_ELEMS + 1 + p] = (float)bestk;

    #pragma unroll
    for (int off = 16; off > 0; off >>= 1)
        lsum += __shfl_down_sync(0xffffffffu, lsum, off);
    if ((tid & 31) == 0) atomicAdd(&g_loss_sum, lsum);

    // last-block loss finalize
    __threadfence();
    __syncthreads();
    if (tid == 0) {
        unsigned tk = atomicAdd(&g_ctr, 1u);
        if (tk == (unsigned)(NBLK - 1)) {
            double s = atomicAdd(&g_loss_sum, 0.0);
            out[ZQ_ELEMS] = (float)(s / (double)ZQ_ELEMS);
        }
    }
}

extern "C" void kernel_launch(void* const* d_in, const int* in_sizes, int n_in,
                              void* d_out, int out_size) {
    const float* z   = (const float*)d_in[0];   // z_e (64,64,64,64) f32
    const float* emb = (const float*)d_in[1];   // emb_weight (512,64) f32
    float* out = (float*)d_out;

    cudaFuncSetAttribute(vq_main, cudaFuncAttributeMaxDynamicSharedMemorySize, SM_TOTAL);
    vq_prep<<<1, KCODES>>>(emb);
    vq_main<<<NBLK, TPB, SM_TOTAL>>>(z, emb, out);
}

// round 9
// speedup vs baseline: 1.2082x; 1.1954x over previous
#include <cuda_runtime.h>
#include <cuda_bf16.h>
#include <cstdint>

#define KCODES 512
#define DDIM 64
#define HW 4096
#define MPTS 262144
#define ZQ_ELEMS 16777216
#define TPB 256
#define NBLK (MPTS / TPB)        // 1024 CTAs, 256 points each

// smem layout (bytes)
#define SM_ESQ 0                 // 512 f32
#define SM_THR 2048              // 256 f32
#define SM_CNT 3072              // 256 u32
#define SM_CAND 4096             // 256 * 8 u32 = 8192
#define SM_A 12288               // 256 rows * 128B bf16 z tile (swizzled)
#define SM_B 45056               // 512 rows * 128B bf16 codebook (swizzled)
#define SM_TOTAL 110592          // 108 KB -> 2 CTAs/SM

#define TAU 4.0e-3f
#define CAND_MAX 8

__device__ double g_loss_sum;
__device__ unsigned g_ctr;
__device__ float g_esq[KCODES];
__device__ __align__(16) __nv_bfloat16 g_embbf[KCODES * DDIM];

// ---- prep: e_sq (exact sequential fp32) + bf16 codebook ----
__global__ void vq_prep(const float* __restrict__ emb) {
    int k = threadIdx.x;                     // 512 threads
    const float* row = emb + k * DDIM;
    float q = 0.f;
    #pragma unroll
    for (int d = 0; d < DDIM; d++) {
        float v = row[d];
        q = __fadd_rn(q, __fmul_rn(v, v));
        g_embbf[k * DDIM + d] = __float2bfloat16(v);
    }
    g_esq[k] = q;
    if (k == 0) { g_loss_sum = 0.0; g_ctr = 0u; }
}

// ---- helpers ----
__device__ __forceinline__ uint32_t smem_u32(const void* p) {
    uint32_t a;
    asm("{ .reg .u64 t; cvta.to.shared.u64 t, %1; cvt.u32.u64 %0, t; }"
        : "=r"(a) : "l"(p));
    return a;
}
// packed bf16x2: lo = a, hi = b
__device__ __forceinline__ uint32_t bf16x2(float a, float b) {
    uint32_t r;
    asm("cvt.rn.bf16x2.f32 %0, %1, %2;" : "=r"(r) : "f"(b), "f"(a));
    return r;
}
__device__ __forceinline__ void ldsm_x4(uint32_t addr, uint32_t& r0, uint32_t& r1,
                                        uint32_t& r2, uint32_t& r3) {
    asm volatile("ldmatrix.sync.aligned.m8n8.x4.shared.b16 {%0,%1,%2,%3}, [%4];"
                 : "=r"(r0), "=r"(r1), "=r"(r2), "=r"(r3) : "r"(addr));
}
__device__ __forceinline__ void mma_bf16(float& d0, float& d1, float& d2, float& d3,
                                         uint32_t a0, uint32_t a1, uint32_t a2, uint32_t a3,
                                         uint32_t b0, uint32_t b1) {
    asm volatile(
        "mma.sync.aligned.m16n8k16.row.col.f32.bf16.bf16.f32 "
        "{%0,%1,%2,%3}, {%4,%5,%6,%7}, {%8,%9}, {%0,%1,%2,%3};"
        : "+f"(d0), "+f"(d1), "+f"(d2), "+f"(d3)
        : "r"(a0), "r"(a1), "r"(a2), "r"(a3), "r"(b0), "r"(b1));
}
// exact reference distance pieces
__device__ __forceinline__ float exact_dist(float S, float esq, float dot) {
    return __fsub_rn(__fadd_rn(S, esq), __fmul_rn(2.0f, dot));
}

__global__ __launch_bounds__(TPB, 2)
void vq_main(const float* __restrict__ z, const float* __restrict__ emb,
             float* __restrict__ out) {
    extern __shared__ char smem[];
    const uint32_t sb = smem_u32(smem);
    const int tid = threadIdx.x;
    const int lane = tid & 31, wid = tid >> 5;
    const int g = lane >> 2, t = lane & 3;
    const int wbase = wid * 32;

    float* sm_esq = (float*)(smem + SM_ESQ);
    float* sm_thr = (float*)(smem + SM_THR);
    unsigned* sm_cnt = (unsigned*)(smem + SM_CNT);
    unsigned* sm_cand = (unsigned*)(smem + SM_CAND);

    for (int i = tid; i < KCODES; i += TPB) sm_esq[i] = g_esq[i];
    sm_cnt[tid] = 0u;

    const int p  = blockIdx.x * TPB + tid;
    const int n  = p >> 12;
    const int hw = p & (HW - 1);
    const float* zp = z + (size_t)n * (DDIM * HW) + hw;

    // Phase A: stream z -> z_sq (sequential fp32) + bf16 A tile (8 floats live)
    float S = 0.f;
    #pragma unroll
    for (int j = 0; j < 8; j++) {
        float v[8];
        #pragma unroll
        for (int e = 0; e < 8; e++) v[e] = zp[(8 * j + e) * HW];
        #pragma unroll
        for (int e = 0; e < 8; e++) S = __fadd_rn(S, __fmul_rn(v[e], v[e]));
        uint32_t w0 = bf16x2(v[0], v[1]);
        uint32_t w1 = bf16x2(v[2], v[3]);
        uint32_t w2 = bf16x2(v[4], v[5]);
        uint32_t w3 = bf16x2(v[6], v[7]);
        uint32_t a = sb + SM_A + (uint32_t)tid * 128 + (uint32_t)((j ^ (tid & 7)) << 4);
        asm volatile("st.shared.v4.b32 [%0], {%1,%2,%3,%4};"
                     :: "r"(a), "r"(w0), "r"(w1), "r"(w2), "r"(w3) : "memory");
    }

    // B tile: 4096 granules / 256 threads = 16 iters
    const uint4* gb = (const uint4*)g_embbf;
    #pragma unroll 4
    for (int it = 0; it < 16; it++) {
        uint32_t i16 = (uint32_t)(it * TPB + tid);
        uint4 v = gb[i16];
        uint32_t row = i16 >> 3, j = i16 & 7;
        uint32_t a = sb + SM_B + row * 128 + ((j ^ (row & 7)) << 4);
        asm volatile("st.shared.v4.b32 [%0], {%1,%2,%3,%4};"
                     :: "r"(a), "r"(v.x), "r"(v.y), "r"(v.z), "r"(v.w) : "memory");
    }
    __syncthreads();

    // A fragments: 2 m-tiles x 4 k-steps
    uint32_t afr[2][4][4];
    {
        const int sub = lane >> 3;
        const int rowo = (lane & 7) + ((sub & 1) << 3);
        #pragma unroll
        for (int m = 0; m < 2; m++) {
            #pragma unroll
            for (int kc = 0; kc < 4; kc++) {
                int row = wbase + 16 * m + rowo;
                int gran = 2 * kc + (sub >> 1);
                uint32_t a = sb + SM_A + (uint32_t)row * 128
                           + (uint32_t)((gran ^ (row & 7)) << 4);
                ldsm_x4(a, afr[m][kc][0], afr[m][kc][1], afr[m][kc][2], afr[m][kc][3]);
            }
        }
    }

    const int brow = lane & 7;
    const int bsub = lane >> 3;
    const float INF = __int_as_float(0x7f800000);

    // Pass 1: MMA sweep, per-fragment-row min only
    float mn0 = INF, mn1 = INF, mn2 = INF, mn3 = INF;
    #pragma unroll 1
    for (int nt = 0; nt < 64; nt++) {
        uint32_t b[8];
        #pragma unroll
        for (int kk = 0; kk < 2; kk++) {
            int row = nt * 8 + brow;
            int gran = 4 * kk + bsub;
            uint32_t a = sb + SM_B + (uint32_t)row * 128
                       + (uint32_t)((gran ^ (row & 7)) << 4);
            ldsm_x4(a, b[4*kk], b[4*kk+1], b[4*kk+2], b[4*kk+3]);
        }
        float2 e2 = *(const float2*)(sm_esq + nt * 8 + 2 * t);
        #pragma unroll
        for (int m = 0; m < 2; m++) {
            float dA0 = 0.f, dA1 = 0.f, dA2 = 0.f, dA3 = 0.f;
            float dB0 = 0.f, dB1 = 0.f, dB2 = 0.f, dB3 = 0.f;
            mma_bf16(dA0, dA1, dA2, dA3, afr[m][0][0], afr[m][0][1], afr[m][0][2], afr[m][0][3], b[0], b[1]);
            mma_bf16(dB0, dB1, dB2, dB3, afr[m][1][0], afr[m][1][1], afr[m][1][2], afr[m][1][3], b[2], b[3]);
            mma_bf16(dA0, dA1, dA2, dA3, afr[m][2][0], afr[m][2][1], afr[m][2][2], afr[m][2][3], b[4], b[5]);
            mma_bf16(dB0, dB1, dB2, dB3, afr[m][3][0], afr[m][3][1], afr[m][3][2], afr[m][3][3], b[6], b[7]);
            float s0 = fmaf(-2.f, dA0 + dB0, e2.x);
            float s1 = fmaf(-2.f, dA1 + dB1, e2.y);
            float s2 = fmaf(-2.f, dA2 + dB2, e2.x);
            float s3 = fmaf(-2.f, dA3 + dB3, e2.y);
            if (m == 0) { mn0 = fminf(mn0, fminf(s0, s1)); mn1 = fminf(mn1, fminf(s2, s3)); }
            else        { mn2 = fminf(mn2, fminf(s0, s1)); mn3 = fminf(mn3, fminf(s2, s3)); }
        }
    }
    #pragma unroll
    for (int off = 1; off <= 2; off <<= 1) {
        mn0 = fminf(mn0, __shfl_xor_sync(0xffffffffu, mn0, off));
        mn1 = fminf(mn1, __shfl_xor_sync(0xffffffffu, mn1, off));
        mn2 = fminf(mn2, __shfl_xor_sync(0xffffffffu, mn2, off));
        mn3 = fminf(mn3, __shfl_xor_sync(0xffffffffu, mn3, off));
    }
    if (t == 0) {
        sm_thr[wbase + g]      = mn0 + TAU;
        sm_thr[wbase + 8 + g]  = mn1 + TAU;
        sm_thr[wbase + 16 + g] = mn2 + TAU;
        sm_thr[wbase + 24 + g] = mn3 + TAU;
    }
    __syncthreads();

    const float tA = sm_thr[wbase + g];
    const float tB = sm_thr[wbase + 8 + g];
    const float tC = sm_thr[wbase + 16 + g];
    const float tD = sm_thr[wbase + 24 + g];

    // Pass 2: identical MMA sweep (bitwise same scores); push candidates
    #pragma unroll 1
    for (int nt = 0; nt < 64; nt++) {
        uint32_t b[8];
        #pragma unroll
        for (int kk = 0; kk < 2; kk++) {
            int row = nt * 8 + brow;
            int gran = 4 * kk + bsub;
            uint32_t a = sb + SM_B + (uint32_t)row * 128
                       + (uint32_t)((gran ^ (row & 7)) << 4);
            ldsm_x4(a, b[4*kk], b[4*kk+1], b[4*kk+2], b[4*kk+3]);
        }
        float2 e2 = *(const float2*)(sm_esq + nt * 8 + 2 * t);
        #pragma unroll
        for (int m = 0; m < 2; m++) {
            float dA0 = 0.f, dA1 = 0.f, dA2 = 0.f, dA3 = 0.f;
            float dB0 = 0.f, dB1 = 0.f, dB2 = 0.f, dB3 = 0.f;
            mma_bf16(dA0, dA1, dA2, dA3, afr[m][0][0], afr[m][0][1], afr[m][0][2], afr[m][0][3], b[0], b[1]);
            mma_bf16(dB0, dB1, dB2, dB3, afr[m][1][0], afr[m][1][1], afr[m][1][2], afr[m][1][3], b[2], b[3]);
            mma_bf16(dA0, dA1, dA2, dA3, afr[m][2][0], afr[m][2][1], afr[m][2][2], afr[m][2][3], b[4], b[5]);
            mma_bf16(dB0, dB1, dB2, dB3, afr[m][3][0], afr[m][3][1], afr[m][3][2], afr[m][3][3], b[6], b[7]);
            float s0 = fmaf(-2.f, dA0 + dB0, e2.x);
            float s1 = fmaf(-2.f, dA1 + dB1, e2.y);
            float s2 = fmaf(-2.f, dA2 + dB2, e2.x);
            float s3 = fmaf(-2.f, dA3 + dB3, e2.y);
            const float thrLo = m ? tC : tA;
            const float thrHi = m ? tD : tB;
            const int rowLo = wbase + 16 * m + g;
            const int rowHi = rowLo + 8;
            const int kbase = nt * 8 + 2 * t;
            if (s0 < thrLo) { unsigned ix = atomicAdd(&sm_cnt[rowLo], 1u);
                              if (ix < CAND_MAX) sm_cand[rowLo * CAND_MAX + ix] = kbase; }
            if (s1 < thrLo) { unsigned ix = atomicAdd(&sm_cnt[rowLo], 1u);
                              if (ix < CAND_MAX) sm_cand[rowLo * CAND_MAX + ix] = kbase + 1; }
            if (s2 < thrHi) { unsigned ix = atomicAdd(&sm_cnt[rowHi], 1u);
                              if (ix < CAND_MAX) sm_cand[rowHi * CAND_MAX + ix] = kbase; }
            if (s3 < thrHi) { unsigned ix = atomicAdd(&sm_cnt[rowHi], 1u);
                              if (ix < CAND_MAX) sm_cand[rowHi * CAND_MAX + ix] = kbase + 1; }
        }
    }
    __syncthreads();

    // Epilogue: pick bestk (cnt==1 fast path; chunked exact rescore otherwise)
    const unsigned cnt = sm_cnt[tid];
    int bestk;
    if (cnt == 1u) {
        bestk = (int)sm_cand[tid * CAND_MAX];
    } else if (cnt <= CAND_MAX) {
        int kc[CAND_MAX];
        #pragma unroll
        for (int c = 0; c < CAND_MAX; c++)
            kc[c] = (c < (int)cnt) ? (int)sm_cand[tid * CAND_MAX + c] : 0;
        float dot[CAND_MAX];
        #pragma unroll
        for (int c = 0; c < CAND_MAX; c++) dot[c] = 0.f;
        #pragma unroll 1
        for (int j = 0; j < 8; j++) {
            float zc[8];
            #pragma unroll
            for (int e = 0; e < 8; e++) zc[e] = zp[(8 * j + e) * HW];
            #pragma unroll
            for (int c = 0; c < CAND_MAX; c++) {
                if (c < (int)cnt) {
                    const float* er = emb + kc[c] * DDIM + 8 * j;
                    #pragma unroll
                    for (int e = 0; e < 8; e++)
                        dot[c] = __fmaf_rn(zc[e], er[e], dot[c]);
                }
            }
        }
        float bestd = INF; bestk = KCODES;
        #pragma unroll
        for (int c = 0; c < CAND_MAX; c++) {
            if (c < (int)cnt) {
                float dist = exact_dist(S, sm_esq[kc[c]], dot[c]);
                if (dist < bestd || (dist == bestd && kc[c] < bestk)) {
                    bestd = dist; bestk = kc[c];
                }
            }
        }
    } else {
        // overflow fallback (statistically never): exact full scan, chunked
        float bestd = INF; bestk = 0;
        for (int k0 = 0; k0 < KCODES; k0 += 8) {
            float dot[8];
            #pragma unroll
            for (int c = 0; c < 8; c++) dot[c] = 0.f;
            #pragma unroll 1
            for (int j = 0; j < 8; j++) {
                float zc[8];
                #pragma unroll
                for (int e = 0; e < 8; e++) zc[e] = zp[(8 * j + e) * HW];
                #pragma unroll
                for (int c = 0; c < 8; c++) {
                    const float* er = emb + (k0 + c) * DDIM + 8 * j;
                    #pragma unroll
                    for (int e = 0; e < 8; e++)
                        dot[c] = __fmaf_rn(zc[e], er[e], dot[c]);
                }
            }
            #pragma unroll
            for (int c = 0; c < 8; c++) {
                float dist = exact_dist(S, sm_esq[k0 + c], dot[c]);
                if (dist < bestd) { bestd = dist; bestk = k0 + c; }  // ascending k
            }
        }
    }

    // Output pass: z_q (straight-through), fp32 loss, index — chunked streams
    const float* er = emb + bestk * DDIM;
    float* outz = out + (size_t)n * (DDIM * HW) + hw;
    float lsum = 0.f;
    #pragma unroll 1
    for (int j = 0; j < 8; j++) {
        float zc[8], ec[8];
        #pragma unroll
        for (int e = 0; e < 8; e++) zc[e] = zp[(8 * j + e) * HW];
        #pragma unroll
        for (int e = 0; e < 8; e++) ec[e] = er[8 * j + e];
        #pragma unroll
        for (int e = 0; e < 8; e++) {
            float v = zc[e], q = ec[e];
            outz[(8 * j + e) * HW] = __fadd_rn(v, __fsub_rn(q, v)); // fl(z + fl(zq - z))
            float x = __fsub_rn(v, q);
            lsum = __fmaf_rn(x, x, lsum);
        }
    }
    out[ZQ_ELEMS + 1 + p] = (float)bestk;

    #pragma unroll
    for (int off = 16; off > 0; off >>= 1)
        lsum += __shfl_down_sync(0xffffffffu, lsum, off);
    if ((tid & 31) == 0) atomicAdd(&g_loss_sum, (double)lsum);

    // last-block loss finalize
    __threadfence();
    __syncthreads();
    if (tid == 0) {
        unsigned tk = atomicAdd(&g_ctr, 1u);
        if (tk == (unsigned)(NBLK - 1)) {
            double s = atomicAdd(&g_loss_sum, 0.0);
            out[ZQ_ELEMS] = (float)(s / (double)ZQ_ELEMS);
        }
    }
}

extern "C" void kernel_launch(void* const* d_in, const int* in_sizes, int n_in,
                              void* d_out, int out_size) {
    const float* z   = (const float*)d_in[0];   // z_e (64,64,64,64) f32
    const float* emb = (const float*)d_in[1];   // emb_weight (512,64) f32
    float* out = (float*)d_out;

    cudaFuncSetAttribute(vq_main, cudaFuncAttributeMaxDynamicSharedMemorySize, SM_TOTAL);
    vq_prep<<<1, KCODES>>>(emb);
    vq_main<<<NBLK, TPB, SM_TOTAL>>>(z, emb, out);
}